// round 2
// baseline (speedup 1.0000x reference)
#include <cuda_runtime.h>

#define EPS 1e-8f

// Scratch (no allocation allowed): intermediates, split-K partials, row sums.
__device__ float g_h1[256 * 1024];
__device__ float g_h2[256 * 1024];
__device__ float g_pC[8 * 256 * 128];
__device__ float g_Sx[256];
__device__ float g_Sh1[256];
__device__ float g_Sh2[256];
__device__ float g_Sw1[1024];
__device__ float g_Sw2[1024];
__device__ float g_Sw3[128];

// ---------------------------------------------------------------------------
// Row-sum kernel: S[row] = sum_k A[row,k].  Tree-reduced (accurate + fast).
// D must be a multiple of 4*blockDim.x is NOT required (grid-stride on quads).
__global__ void rowsum_kernel(const float* __restrict__ A,
                              float* __restrict__ S, int D)
{
    const int row = blockIdx.x;
    const float4* a = reinterpret_cast<const float4*>(A + (size_t)row * D);
    const int nq = D >> 2;
    float s = 0.0f;
    for (int q = threadIdx.x; q < nq; q += blockDim.x) {
        float4 v = a[q];
        s += (v.x + v.y) + (v.z + v.w);
    }
#pragma unroll
    for (int o = 16; o > 0; o >>= 1) s += __shfl_xor_sync(0xFFFFFFFFu, s, o);
    __shared__ float ws[32];
    const int lane = threadIdx.x & 31, w = threadIdx.x >> 5;
    if (lane == 0) ws[w] = s;
    __syncthreads();
    if (w == 0) {
        s = (lane < (int)(blockDim.x >> 5)) ? ws[lane] : 0.0f;
#pragma unroll
        for (int o = 16; o > 0; o >>= 1) s += __shfl_xor_sync(0xFFFFFFFFu, s, o);
        if (lane == 0) S[row] = s;
    }
}

// ---------------------------------------------------------------------------
// Tversky "min-plus" tile kernel.
//   C[m,n] = sum_k min(X[m,k], W[n,k])  over k in [z*kspan, (z+1)*kspan)
//   If !SPLIT: out[m,n] = relu?( C / (0.5*(Sx[m]+Sw[n]) + EPS) )
//   If SPLIT:  pC[z,m,n] = C   (combine kernel finishes the job)
// Tiles: BM=32 (batch), BN=64 (prototypes), DK=16, micro-tile 4x4, 128 thr.
template <int BM, int BN, int TM, int TN, int DK, bool SPLIT, bool RELU>
__global__ __launch_bounds__((BM / TM) * (BN / TN))
void tversky_min_kernel(const float* __restrict__ X,
                        const float* __restrict__ W,
                        const float* __restrict__ Sx,
                        const float* __restrict__ Sw,
                        float* __restrict__ out,
                        float* __restrict__ pC,
                        int B, int O, int D, int kspan)
{
    constexpr int NTX = BN / TN;           // 16
    constexpr int NTY = BM / TM;           // 8
    constexpr int NT  = NTX * NTY;         // 128
    constexpr int QPR = DK / 4;            // float4 per tile row (4)

    static_assert(BM * QPR == NT, "X loader: 1 float4/thread");
    static_assert(BN * QPR == 2 * NT, "W loader: 2 float4/thread");

    const int tid = threadIdx.x;
    const int tx  = tid % NTX;
    const int ty  = tid / NTX;
    const int m0  = blockIdx.y * BM;
    const int n0  = blockIdx.x * BN;
    const int k0  = blockIdx.z * kspan;

    // X tile kept row-major (broadcast LDS in compute); W tile transposed.
    __shared__ __align__(16) float Xs[BM][DK];
    __shared__ __align__(16) float Ws[DK][BN];

    // Loader coordinates (coalesced gmem).
    const int xr = tid / QPR, xq = tid % QPR;          // X: row 0..31, quad 0..3
    const int wr = tid / QPR, wq = tid % QPR;          // W: row 0..31 (+32), quad

    const float4* Xg  = reinterpret_cast<const float4*>(X + (size_t)(m0 + xr) * D + k0) + xq;
    const float4* Wg0 = reinterpret_cast<const float4*>(W + (size_t)(n0 + wr) * D + k0) + wq;
    const float4* Wg1 = reinterpret_cast<const float4*>(W + (size_t)(n0 + wr + 32) * D + k0) + wq;
    constexpr int QSTEP = 0; (void)QSTEP;
    const int qstride = DK / 4;                        // float4 step per k-tile

    float acc[TM][TN];
#pragma unroll
    for (int i = 0; i < TM; i++)
#pragma unroll
        for (int j = 0; j < TN; j++) acc[i][j] = 0.0f;

    const int ntiles = kspan / DK;

    // Register prefetch of tile 0.
    float4 xv = Xg[0];
    float4 wv0 = Wg0[0];
    float4 wv1 = Wg1[0];

    for (int t = 0; t < ntiles; t++) {
        // Store prefetched tile into smem.
        *reinterpret_cast<float4*>(&Xs[xr][xq * 4]) = xv;
        Ws[wq * 4 + 0][wr] = wv0.x;
        Ws[wq * 4 + 1][wr] = wv0.y;
        Ws[wq * 4 + 2][wr] = wv0.z;
        Ws[wq * 4 + 3][wr] = wv0.w;
        Ws[wq * 4 + 0][wr + 32] = wv1.x;
        Ws[wq * 4 + 1][wr + 32] = wv1.y;
        Ws[wq * 4 + 2][wr + 32] = wv1.z;
        Ws[wq * 4 + 3][wr + 32] = wv1.w;
        __syncthreads();

        // Prefetch next tile (latency hidden behind compute below).
        if (t + 1 < ntiles) {
            xv  = Xg[(t + 1) * qstride];
            wv0 = Wg0[(t + 1) * qstride];
            wv1 = Wg1[(t + 1) * qstride];
        }

        // Compute on current tile.
#pragma unroll
        for (int kk = 0; kk < DK; kk += 4) {
            float xk[TM][4];
#pragma unroll
            for (int i = 0; i < TM; i++) {
                float4 v = *reinterpret_cast<const float4*>(&Xs[ty * TM + i][kk]);
                xk[i][0] = v.x; xk[i][1] = v.y; xk[i][2] = v.z; xk[i][3] = v.w;
            }
            float wk[4][TN];
#pragma unroll
            for (int c = 0; c < 4; c++) {
                float4 v = *reinterpret_cast<const float4*>(&Ws[kk + c][tx * TN]);
                wk[c][0] = v.x; wk[c][1] = v.y; wk[c][2] = v.z; wk[c][3] = v.w;
            }
#pragma unroll
            for (int c = 0; c < 4; c++)
#pragma unroll
                for (int i = 0; i < TM; i++)
#pragma unroll
                    for (int j = 0; j < TN; j++)
                        acc[i][j] += fminf(xk[i][c], wk[c][j]);
        }
        __syncthreads();
    }

    if (!SPLIT) {
        float sxm[TM], swn[TN];
#pragma unroll
        for (int i = 0; i < TM; i++) sxm[i] = Sx[m0 + ty * TM + i];
#pragma unroll
        for (int j = 0; j < TN; j++) swn[j] = Sw[n0 + tx * TN + j];
#pragma unroll
        for (int i = 0; i < TM; i++) {
            float4 o4;
            float* op = &o4.x;
#pragma unroll
            for (int j = 0; j < TN; j++) {
                float s = acc[i][j] / (0.5f * (sxm[i] + swn[j]) + EPS);
                if (RELU) s = fmaxf(s, 0.0f);
                op[j] = s;
            }
            *reinterpret_cast<float4*>(out + (size_t)(m0 + ty * TM + i) * O
                                       + (n0 + tx * TN)) = o4;
        }
    } else {
        const size_t zb = (size_t)blockIdx.z * B * O;
#pragma unroll
        for (int i = 0; i < TM; i++) {
            float4 o4;
            float* op = &o4.x;
#pragma unroll
            for (int j = 0; j < TN; j++) op[j] = acc[i][j];
            *reinterpret_cast<float4*>(pC + zb + (size_t)(m0 + ty * TM + i) * O
                                       + (n0 + tx * TN)) = o4;
        }
    }
}

// ---------------------------------------------------------------------------
// Combine split-K partials + epilogue (final layer: no relu).
__global__ void combine_kernel(const float* __restrict__ pC,
                               const float* __restrict__ Sx,
                               const float* __restrict__ Sw,
                               float* __restrict__ out,
                               int O, int BO, int nz)
{
    int i = blockIdx.x * blockDim.x + threadIdx.x;
    if (i >= BO) return;
    float c = 0.0f;
    for (int z = 0; z < nz; z++) c += pC[(size_t)z * BO + i];
    const int m = i / O, n = i % O;
    out[i] = c / (0.5f * (Sx[m] + Sw[n]) + EPS);
}

// ---------------------------------------------------------------------------
extern "C" void kernel_launch(void* const* d_in, const int* in_sizes, int n_in,
                              void* d_out, int out_size)
{
    const float* x  = (const float*)d_in[0];   // [256, 1024]
    const float* W1 = (const float*)d_in[1];   // [1024, 1024]
    const float* W2 = (const float*)d_in[2];   // [1024, 1024]
    const float* W3 = (const float*)d_in[3];   // [128, 1024]
    float* out = (float*)d_out;                // [256, 128]

    const int B = 256, H = 1024, C = 128, D = 1024;

    float *h1, *h2, *pC, *Sx, *Sh1, *Sh2, *Sw1, *Sw2, *Sw3;
    cudaGetSymbolAddress((void**)&h1,  g_h1);
    cudaGetSymbolAddress((void**)&h2,  g_h2);
    cudaGetSymbolAddress((void**)&pC,  g_pC);
    cudaGetSymbolAddress((void**)&Sx,  g_Sx);
    cudaGetSymbolAddress((void**)&Sh1, g_Sh1);
    cudaGetSymbolAddress((void**)&Sh2, g_Sh2);
    cudaGetSymbolAddress((void**)&Sw1, g_Sw1);
    cudaGetSymbolAddress((void**)&Sw2, g_Sw2);
    cudaGetSymbolAddress((void**)&Sw3, g_Sw3);

    constexpr int BM = 32, BN = 64, TM = 4, TN = 4, DK = 16;
    constexpr int NT = (BM / TM) * (BN / TN);  // 128

    // Row sums of the static inputs (cheap, L2-resident).
    rowsum_kernel<<<B, 128>>>(x,  Sx,  D);
    rowsum_kernel<<<H, 128>>>(W1, Sw1, D);
    rowsum_kernel<<<H, 128>>>(W2, Sw2, H);
    rowsum_kernel<<<C, 128>>>(W3, Sw3, H);

    // Layer 1: x vs W1 -> h1 (relu)
    {
        dim3 grid(H / BN, B / BM, 1);
        tversky_min_kernel<BM, BN, TM, TN, DK, false, true>
            <<<grid, NT>>>(x, W1, Sx, Sw1, h1, nullptr, B, H, D, D);
    }
    rowsum_kernel<<<B, 128>>>(h1, Sh1, H);

    // Layer 2: h1 vs W2 -> h2 (relu)
    {
        dim3 grid(H / BN, B / BM, 1);
        tversky_min_kernel<BM, BN, TM, TN, DK, false, true>
            <<<grid, NT>>>(h1, W2, Sh1, Sw2, h2, nullptr, B, H, H, H);
    }
    rowsum_kernel<<<B, 128>>>(h2, Sh2, H);

    // Layer 3: h2 vs W3 -> out (no relu), split-K=8 for grid fill.
    {
        const int NZ = 8;
        dim3 grid(C / BN, B / BM, NZ);
        tversky_min_kernel<BM, BN, TM, TN, DK, true, false>
            <<<grid, NT>>>(h2, W3, nullptr, nullptr, nullptr, pC, B, C, H, H / NZ);
        combine_kernel<<<(B * C + 255) / 256, 256>>>(pC, Sh2, Sw3, out, C, B * C, NZ);
    }
}

// round 5
// speedup vs baseline: 1.3345x; 1.3345x over previous
// R3 re-bench attempt #2: two consecutive GB300 container infra failures
// (same error also occurred in R0 with an empty stub). Kernel unchanged from R3.
#include <cuda_runtime.h>

#define EPS 1e-8f

// Scratch (no allocation allowed).
__device__ float g_h1[256 * 1024];
__device__ float g_h2[256 * 1024];
__device__ float g_pC[8 * 256 * 128];
__device__ float g_Sx[256];
__device__ float g_Sh1[256];
__device__ float g_Sh2[256];
__device__ float g_Sw1[1024];
__device__ float g_Sw2[1024];
__device__ float g_Sw3[128];

// ---------------------------------------------------------------------------
// Row-sum: S[row] = sum_k A[row,k], tree-reduced. 128 threads per row-block.
__device__ __forceinline__ void rowsum_body(const float* __restrict__ A,
                                            float* __restrict__ S,
                                            int row, int D)
{
    const float4* a = reinterpret_cast<const float4*>(A + (size_t)row * D);
    const int nq = D >> 2;
    float s = 0.0f;
    for (int q = threadIdx.x; q < nq; q += blockDim.x) {
        float4 v = a[q];
        s += (v.x + v.y) + (v.z + v.w);
    }
#pragma unroll
    for (int o = 16; o > 0; o >>= 1) s += __shfl_xor_sync(0xFFFFFFFFu, s, o);
    __shared__ float ws[32];
    const int lane = threadIdx.x & 31, w = threadIdx.x >> 5;
    if (lane == 0) ws[w] = s;
    __syncthreads();
    if (w == 0) {
        s = (lane < (int)(blockDim.x >> 5)) ? ws[lane] : 0.0f;
#pragma unroll
        for (int o = 16; o > 0; o >>= 1) s += __shfl_xor_sync(0xFFFFFFFFu, s, o);
        if (lane == 0) S[row] = s;
    }
}

__global__ void rowsum_kernel(const float* __restrict__ A,
                              float* __restrict__ S, int D)
{
    rowsum_body(A, S, blockIdx.x, D);
}

// Fused row-sums for the four static inputs (all have D=1024).
__global__ void rowsum4_kernel(const float* __restrict__ x,  float* __restrict__ Sx,
                               const float* __restrict__ W1, float* __restrict__ Sw1,
                               const float* __restrict__ W2, float* __restrict__ Sw2,
                               const float* __restrict__ W3, float* __restrict__ Sw3,
                               int D)
{
    int b = blockIdx.x;
    if (b < 256)            rowsum_body(x,  Sx,  b,          D);
    else if (b < 256+1024)  rowsum_body(W1, Sw1, b - 256,    D);
    else if (b < 256+2048)  rowsum_body(W2, Sw2, b - 1280,   D);
    else                    rowsum_body(W3, Sw3, b - 2304,   D);
}

// ---------------------------------------------------------------------------
// Tversky min-sum tile kernel.
//   C[m,n] = sum_k min(X[m,k], W[n,k]) over k in [z*kspan, (z+1)*kspan)
//   !SPLIT: out[m,n] = relu?( C / (0.5*(Sx[m]+Sw[n]) + EPS) )
//   SPLIT:  pC[z,m,n] = C
// BM=32, BN=64, DK=32, 256 threads, micro-tile TM=2 x TN=4, double-buffered.
template <int BM, int BN, int TM, int TN, int DK, bool SPLIT, bool RELU>
__global__ __launch_bounds__((BM / TM) * (BN / TN))
void tversky_min_kernel(const float* __restrict__ X,
                        const float* __restrict__ W,
                        const float* __restrict__ Sx,
                        const float* __restrict__ Sw,
                        float* __restrict__ out,
                        float* __restrict__ pC,
                        int B, int O, int D, int kspan)
{
    constexpr int NTX = BN / TN;           // 16
    constexpr int NTY = BM / TM;           // 16
    constexpr int NT  = NTX * NTY;         // 256
    constexpr int QPR = DK / 4;            // 8 float4 per tile row

    static_assert(BM * QPR == NT, "X loader: 1 float4/thread");
    static_assert(BN * QPR == 2 * NT, "W loader: 2 float4/thread");

    constexpr int XSTR = BM + 2;           // 34 floats: conflict-light, 8B-aligned rows
    constexpr int WSTR = BN + 8;           // 72 floats: 16B-aligned rows for LDS.128

    const int tid = threadIdx.x;
    const int tx  = tid % NTX;
    const int ty  = tid / NTX;
    const int m0  = blockIdx.y * BM;
    const int n0  = blockIdx.x * BN;
    const int k0  = blockIdx.z * kspan;

    __shared__ __align__(16) float Xs[2][DK][XSTR];
    __shared__ __align__(16) float Ws[2][DK][WSTR];

    const int xr = tid >> 3, xq = tid & 7;     // X: row 0..31, quad 0..7
    const int wr = tid >> 3, wq = tid & 7;     // W: rows wr, wr+32

    const float4* Xg  = reinterpret_cast<const float4*>(X + (size_t)(m0 + xr) * D + k0) + xq;
    const float4* Wg0 = reinterpret_cast<const float4*>(W + (size_t)(n0 + wr) * D + k0) + wq;
    const float4* Wg1 = reinterpret_cast<const float4*>(W + (size_t)(n0 + wr + 32) * D + k0) + wq;

    float acc[TM][TN];
#pragma unroll
    for (int i = 0; i < TM; i++)
#pragma unroll
        for (int j = 0; j < TN; j++) acc[i][j] = 0.0f;

    const int ntiles = kspan / DK;

    float4 xv  = Xg[0];
    float4 wv0 = Wg0[0];
    float4 wv1 = Wg1[0];

    for (int t = 0; t < ntiles; t++) {
        const int buf = t & 1;

        // Store prefetched tile (transposed) into the current buffer.
#pragma unroll
        for (int c = 0; c < 4; c++) {
            Xs[buf][xq * 4 + c][xr]      = (&xv.x)[c];
            Ws[buf][wq * 4 + c][wr]      = (&wv0.x)[c];
            Ws[buf][wq * 4 + c][wr + 32] = (&wv1.x)[c];
        }
        __syncthreads();

        // Prefetch next tile into registers (hidden behind compute).
        if (t + 1 < ntiles) {
            xv  = Xg[(size_t)(t + 1) * QPR];
            wv0 = Wg0[(size_t)(t + 1) * QPR];
            wv1 = Wg1[(size_t)(t + 1) * QPR];
        }

        // Compute: chunk accumulator per tile (2-level accumulation).
        float ch[TM][TN];
#pragma unroll
        for (int i = 0; i < TM; i++)
#pragma unroll
            for (int j = 0; j < TN; j++) ch[i][j] = 0.0f;

#pragma unroll
        for (int k = 0; k < DK; k++) {
            float2 xk = *reinterpret_cast<const float2*>(&Xs[buf][k][ty * TM]);
            float4 wk = *reinterpret_cast<const float4*>(&Ws[buf][k][tx * TN]);
            const float xa[TM] = { xk.x, xk.y };
            const float wa[TN] = { wk.x, wk.y, wk.z, wk.w };
#pragma unroll
            for (int i = 0; i < TM; i++)
#pragma unroll
                for (int j = 0; j < TN; j++)
                    ch[i][j] += fminf(xa[i], wa[j]);
        }
#pragma unroll
        for (int i = 0; i < TM; i++)
#pragma unroll
            for (int j = 0; j < TN; j++) acc[i][j] += ch[i][j];

        __syncthreads();
    }

    if (!SPLIT) {
        float sxm[TM], swn[TN];
#pragma unroll
        for (int i = 0; i < TM; i++) sxm[i] = Sx[m0 + ty * TM + i];
#pragma unroll
        for (int j = 0; j < TN; j++) swn[j] = Sw[n0 + tx * TN + j];
#pragma unroll
        for (int i = 0; i < TM; i++) {
            float4 o4;
            float* op = &o4.x;
#pragma unroll
            for (int j = 0; j < TN; j++) {
                float s = acc[i][j] / (0.5f * (sxm[i] + swn[j]) + EPS);
                if (RELU) s = fmaxf(s, 0.0f);
                op[j] = s;
            }
            *reinterpret_cast<float4*>(out + (size_t)(m0 + ty * TM + i) * O
                                       + (n0 + tx * TN)) = o4;
        }
    } else {
        const size_t zb = (size_t)blockIdx.z * B * O;
#pragma unroll
        for (int i = 0; i < TM; i++) {
            float4 o4;
            float* op = &o4.x;
#pragma unroll
            for (int j = 0; j < TN; j++) op[j] = acc[i][j];
            *reinterpret_cast<float4*>(pC + zb + (size_t)(m0 + ty * TM + i) * O
                                       + (n0 + tx * TN)) = o4;
        }
    }
}

// ---------------------------------------------------------------------------
// Combine split-K partials + epilogue (final layer: no relu).
__global__ void combine_kernel(const float* __restrict__ pC,
                               const float* __restrict__ Sx,
                               const float* __restrict__ Sw,
                               float* __restrict__ out,
                               int O, int BO, int nz)
{
    int i = blockIdx.x * blockDim.x + threadIdx.x;
    if (i >= BO) return;
    float c = 0.0f;
    for (int z = 0; z < nz; z++) c += pC[(size_t)z * BO + i];
    const int m = i / O, n = i % O;
    out[i] = c / (0.5f * (Sx[m] + Sw[n]) + EPS);
}

// ---------------------------------------------------------------------------
extern "C" void kernel_launch(void* const* d_in, const int* in_sizes, int n_in,
                              void* d_out, int out_size)
{
    const float* x  = (const float*)d_in[0];   // [256, 1024]
    const float* W1 = (const float*)d_in[1];   // [1024, 1024]
    const float* W2 = (const float*)d_in[2];   // [1024, 1024]
    const float* W3 = (const float*)d_in[3];   // [128, 1024]
    float* out = (float*)d_out;                // [256, 128]

    const int B = 256, H = 1024, C = 128, D = 1024;

    float *h1, *h2, *pC, *Sx, *Sh1, *Sh2, *Sw1, *Sw2, *Sw3;
    cudaGetSymbolAddress((void**)&h1,  g_h1);
    cudaGetSymbolAddress((void**)&h2,  g_h2);
    cudaGetSymbolAddress((void**)&pC,  g_pC);
    cudaGetSymbolAddress((void**)&Sx,  g_Sx);
    cudaGetSymbolAddress((void**)&Sh1, g_Sh1);
    cudaGetSymbolAddress((void**)&Sh2, g_Sh2);
    cudaGetSymbolAddress((void**)&Sw1, g_Sw1);
    cudaGetSymbolAddress((void**)&Sw2, g_Sw2);
    cudaGetSymbolAddress((void**)&Sw3, g_Sw3);

    constexpr int BM = 32, BN = 64, TM = 2, TN = 4, DK = 32;
    constexpr int NT = (BM / TM) * (BN / TN);  // 256

    // All static row-sums in ONE launch (2432 row-blocks).
    rowsum4_kernel<<<256 + 1024 + 1024 + 128, 128>>>(x, Sx, W1, Sw1, W2, Sw2, W3, Sw3, D);

    // Layer 1: x vs W1 -> h1 (relu)
    {
        dim3 grid(H / BN, B / BM, 1);
        tversky_min_kernel<BM, BN, TM, TN, DK, false, true>
            <<<grid, NT>>>(x, W1, Sx, Sw1, h1, nullptr, B, H, D, D);
    }
    rowsum_kernel<<<B, 128>>>(h1, Sh1, H);

    // Layer 2: h1 vs W2 -> h2 (relu)
    {
        dim3 grid(H / BN, B / BM, 1);
        tversky_min_kernel<BM, BN, TM, TN, DK, false, true>
            <<<grid, NT>>>(h1, W2, Sh1, Sw2, h2, nullptr, B, H, H, H);
    }
    rowsum_kernel<<<B, 128>>>(h2, Sh2, H);

    // Layer 3: h2 vs W3 -> out (no relu), split-K=8 for grid fill.
    {
        const int NZ = 8;
        dim3 grid(C / BN, B / BM, NZ);
        tversky_min_kernel<BM, BN, TM, TN, DK, true, false>
            <<<grid, NT>>>(h2, W3, nullptr, nullptr, nullptr, pC, B, C, H, H / NZ);
        combine_kernel<<<(B * C + 255) / 256, 256>>>(pC, Sh2, Sw3, out, C, B * C, NZ);
    }
}

// round 6
// speedup vs baseline: 1.6696x; 1.2511x over previous
#include <cuda_runtime.h>

#define EPS 1e-8f

// Scratch (no allocation allowed).
__device__ float g_h1[256 * 1024];
__device__ float g_h2[256 * 1024];
__device__ float g_pC[2 * 256 * 1024];   // also fits 16*256*128 for layer 3
__device__ float g_Sx[256];
__device__ float g_Sh1[256];
__device__ float g_Sh2[256];
__device__ float g_Sw1[1024];
__device__ float g_Sw2[1024];
__device__ float g_Sw3[128];

// ---------------------------------------------------------------------------
// Row-sum body (tree-reduced), 128 threads per row-block.
__device__ __forceinline__ void rowsum_body(const float* __restrict__ A,
                                            float* __restrict__ S,
                                            int row, int D)
{
    const float4* a = reinterpret_cast<const float4*>(A + (size_t)row * D);
    const int nq = D >> 2;
    float s = 0.0f;
    for (int q = threadIdx.x; q < nq; q += blockDim.x) {
        float4 v = a[q];
        s += (v.x + v.y) + (v.z + v.w);
    }
#pragma unroll
    for (int o = 16; o > 0; o >>= 1) s += __shfl_xor_sync(0xFFFFFFFFu, s, o);
    __shared__ float ws[32];
    const int lane = threadIdx.x & 31, w = threadIdx.x >> 5;
    if (lane == 0) ws[w] = s;
    __syncthreads();
    if (w == 0) {
        s = (lane < (int)(blockDim.x >> 5)) ? ws[lane] : 0.0f;
#pragma unroll
        for (int o = 16; o > 0; o >>= 1) s += __shfl_xor_sync(0xFFFFFFFFu, s, o);
        if (lane == 0) S[row] = s;
    }
}

// Fused row-sums for the four static inputs (all D=1024).
__global__ void rowsum4_kernel(const float* __restrict__ x,  float* __restrict__ Sx,
                               const float* __restrict__ W1, float* __restrict__ Sw1,
                               const float* __restrict__ W2, float* __restrict__ Sw2,
                               const float* __restrict__ W3, float* __restrict__ Sw3,
                               int D)
{
    int b = blockIdx.x;
    if (b < 256)            rowsum_body(x,  Sx,  b,        D);
    else if (b < 256+1024)  rowsum_body(W1, Sw1, b - 256,  D);
    else if (b < 256+2048)  rowsum_body(W2, Sw2, b - 1280, D);
    else                    rowsum_body(W3, Sw3, b - 2304, D);
}

// ---------------------------------------------------------------------------
// Min-sum partial kernel: pC[z,m,n] = sum_{k in z-slice} min(X[m,k], W[n,k]).
// BM=BN=64, DK=32, 256 threads, micro-tile 4x4, double-buffered smem.
// X tile row-major [m][k] (compute reads 4 k's per row via broadcast LDS.128);
// W tile transposed [k][n].
__global__ __launch_bounds__(256)
void tversky_part_kernel(const float* __restrict__ X,
                         const float* __restrict__ W,
                         float* __restrict__ pC,
                         int B, int O, int D, int kspan)
{
    constexpr int BM = 64, BN = 64, DK = 32, TM = 4, TN = 4;
    constexpr int NTX = BN / TN;          // 16
    constexpr int XSTR = DK + 4;          // 36 floats (16B-aligned rows)
    constexpr int WSTR = BN + 4;          // 68 floats (16B-aligned rows)

    const int tid = threadIdx.x;
    const int tx  = tid % NTX;
    const int ty  = tid / NTX;
    const int m0  = blockIdx.y * BM;
    const int n0  = blockIdx.x * BN;
    const int k0  = blockIdx.z * kspan;

    __shared__ __align__(16) float Xs[2][BM][XSTR];
    __shared__ __align__(16) float Ws[2][DK][WSTR];

    // Loaders: 64 rows x 8 quads = 512 float4 per operand, 2 per thread.
    const int lr = tid >> 3;              // 0..31 (also +32)
    const int lq = tid & 7;               // 0..7

    const float4* Xg0 = reinterpret_cast<const float4*>(X + (size_t)(m0 + lr) * D + k0) + lq;
    const float4* Xg1 = reinterpret_cast<const float4*>(X + (size_t)(m0 + lr + 32) * D + k0) + lq;
    const float4* Wg0 = reinterpret_cast<const float4*>(W + (size_t)(n0 + lr) * D + k0) + lq;
    const float4* Wg1 = reinterpret_cast<const float4*>(W + (size_t)(n0 + lr + 32) * D + k0) + lq;

    float acc[TM][TN];
#pragma unroll
    for (int i = 0; i < TM; i++)
#pragma unroll
        for (int j = 0; j < TN; j++) acc[i][j] = 0.0f;

    const int ntiles = kspan / DK;

    float4 xv0 = Xg0[0], xv1 = Xg1[0];
    float4 wv0 = Wg0[0], wv1 = Wg1[0];

    for (int t = 0; t < ntiles; t++) {
        const int buf = t & 1;

        // X stored row-major (direct float4); W transposed (scalar scatter).
        *reinterpret_cast<float4*>(&Xs[buf][lr][lq * 4])      = xv0;
        *reinterpret_cast<float4*>(&Xs[buf][lr + 32][lq * 4]) = xv1;
#pragma unroll
        for (int c = 0; c < 4; c++) {
            Ws[buf][lq * 4 + c][lr]      = (&wv0.x)[c];
            Ws[buf][lq * 4 + c][lr + 32] = (&wv1.x)[c];
        }
        __syncthreads();

        if (t + 1 < ntiles) {
            const int off = (t + 1) * (DK / 4);
            xv0 = Xg0[off]; xv1 = Xg1[off];
            wv0 = Wg0[off]; wv1 = Wg1[off];
        }

#pragma unroll
        for (int kk = 0; kk < DK; kk += 4) {
            float4 xk[TM];
#pragma unroll
            for (int i = 0; i < TM; i++)
                xk[i] = *reinterpret_cast<const float4*>(&Xs[buf][ty * TM + i][kk]);
            float4 wk[4];
#pragma unroll
            for (int c = 0; c < 4; c++)
                wk[c] = *reinterpret_cast<const float4*>(&Ws[buf][kk + c][tx * TN]);
#pragma unroll
            for (int c = 0; c < 4; c++) {
#pragma unroll
                for (int i = 0; i < TM; i++) {
                    const float xi = (&xk[i].x)[c];
                    acc[i][0] += fminf(xi, wk[c].x);
                    acc[i][1] += fminf(xi, wk[c].y);
                    acc[i][2] += fminf(xi, wk[c].z);
                    acc[i][3] += fminf(xi, wk[c].w);
                }
            }
        }
        __syncthreads();
    }

    const size_t zb = (size_t)blockIdx.z * B * O;
#pragma unroll
    for (int i = 0; i < TM; i++) {
        float4 o4;
        o4.x = acc[i][0]; o4.y = acc[i][1]; o4.z = acc[i][2]; o4.w = acc[i][3];
        *reinterpret_cast<float4*>(pC + zb + (size_t)(m0 + ty * TM + i) * O
                                   + (n0 + tx * TN)) = o4;
    }
}

// ---------------------------------------------------------------------------
// Combine NZ=2 partials + epilogue(+relu) + row-sum of the result (for next layer).
// One block per output row; 256 threads, 4 cols each (O=1024).
__global__ void combine_epi_rowsum_kernel(const float* __restrict__ pC,
                                          const float* __restrict__ Sx,
                                          const float* __restrict__ Sw,
                                          float* __restrict__ h,
                                          float* __restrict__ Sh,
                                          int B, int O)
{
    const int row = blockIdx.x;
    const int j0  = threadIdx.x * 4;
    const size_t plane = (size_t)B * O;
    const size_t base  = (size_t)row * O + j0;

    float4 c0 = *reinterpret_cast<const float4*>(pC + base);
    float4 c1 = *reinterpret_cast<const float4*>(pC + plane + base);
    float4 sw = *reinterpret_cast<const float4*>(Sw + j0);
    const float sx = Sx[row];

    float4 o;
    o.x = fmaxf((c0.x + c1.x) / (0.5f * (sx + sw.x) + EPS), 0.0f);
    o.y = fmaxf((c0.y + c1.y) / (0.5f * (sx + sw.y) + EPS), 0.0f);
    o.z = fmaxf((c0.z + c1.z) / (0.5f * (sx + sw.z) + EPS), 0.0f);
    o.w = fmaxf((c0.w + c1.w) / (0.5f * (sx + sw.w) + EPS), 0.0f);
    *reinterpret_cast<float4*>(h + base) = o;

    // Row-sum of h for the next layer's denominator.
    float s = (o.x + o.y) + (o.z + o.w);
#pragma unroll
    for (int off = 16; off > 0; off >>= 1) s += __shfl_xor_sync(0xFFFFFFFFu, s, off);
    __shared__ float ws[8];
    const int lane = threadIdx.x & 31, w = threadIdx.x >> 5;
    if (lane == 0) ws[w] = s;
    __syncthreads();
    if (w == 0) {
        s = (lane < 8) ? ws[lane] : 0.0f;
#pragma unroll
        for (int off = 4; off > 0; off >>= 1) s += __shfl_xor_sync(0xFFFFFFFFu, s, off);
        if (lane == 0) Sh[row] = s;
    }
}

// Combine NZ partials + epilogue (final layer, no relu, no rowsum).
__global__ void combine_final_kernel(const float* __restrict__ pC,
                                     const float* __restrict__ Sx,
                                     const float* __restrict__ Sw,
                                     float* __restrict__ out,
                                     int O, int BO, int nz)
{
    int i = blockIdx.x * blockDim.x + threadIdx.x;
    if (i >= BO) return;
    float c = 0.0f;
    for (int z = 0; z < nz; z++) c += pC[(size_t)z * BO + i];
    const int m = i / O, n = i % O;
    out[i] = c / (0.5f * (Sx[m] + Sw[n]) + EPS);
}

// ---------------------------------------------------------------------------
extern "C" void kernel_launch(void* const* d_in, const int* in_sizes, int n_in,
                              void* d_out, int out_size)
{
    const float* x  = (const float*)d_in[0];   // [256, 1024]
    const float* W1 = (const float*)d_in[1];   // [1024, 1024]
    const float* W2 = (const float*)d_in[2];   // [1024, 1024]
    const float* W3 = (const float*)d_in[3];   // [128, 1024]
    float* out = (float*)d_out;                // [256, 128]

    const int B = 256, H = 1024, C = 128, D = 1024;

    float *h1, *h2, *pC, *Sx, *Sh1, *Sh2, *Sw1, *Sw2, *Sw3;
    cudaGetSymbolAddress((void**)&h1,  g_h1);
    cudaGetSymbolAddress((void**)&h2,  g_h2);
    cudaGetSymbolAddress((void**)&pC,  g_pC);
    cudaGetSymbolAddress((void**)&Sx,  g_Sx);
    cudaGetSymbolAddress((void**)&Sh1, g_Sh1);
    cudaGetSymbolAddress((void**)&Sh2, g_Sh2);
    cudaGetSymbolAddress((void**)&Sw1, g_Sw1);
    cudaGetSymbolAddress((void**)&Sw2, g_Sw2);
    cudaGetSymbolAddress((void**)&Sw3, g_Sw3);

    // Static row sums in one launch.
    rowsum4_kernel<<<256 + 1024 + 1024 + 128, 128>>>(x, Sx, W1, Sw1, W2, Sw2, W3, Sw3, D);

    // Layer 1: x vs W1, split-K=2 (grid 16x4x2 = 128 CTAs), then fused combine.
    {
        dim3 grid(H / 64, B / 64, 2);
        tversky_part_kernel<<<grid, 256>>>(x, W1, pC, B, H, D, D / 2);
        combine_epi_rowsum_kernel<<<B, 256>>>(pC, Sx, Sw1, h1, Sh1, B, H);
    }
    // Layer 2: h1 vs W2, split-K=2, fused combine.
    {
        dim3 grid(H / 64, B / 64, 2);
        tversky_part_kernel<<<grid, 256>>>(h1, W2, pC, B, H, H, H / 2);
        combine_epi_rowsum_kernel<<<B, 256>>>(pC, Sh1, Sw2, h2, Sh2, B, H);
    }
    // Layer 3: h2 vs W3, split-K=16 (grid 2x4x16 = 128 CTAs), plain combine.
    {
        const int NZ = 16;
        dim3 grid(C / 64, B / 64, NZ);
        tversky_part_kernel<<<grid, 256>>>(h2, W3, pC, B, C, H, H / NZ);
        combine_final_kernel<<<(B * C + 255) / 256, 256>>>(pC, Sh2, Sw3, out, C, B * C, NZ);
    }
}

// round 9
// speedup vs baseline: 1.7352x; 1.0393x over previous
// R8 re-bench attempt #3 of the BN=128/512-thread candidate. Two consecutive
// container infra failures on this source; precedent (R3->R5) shows identical
// source failing twice then passing. Kernel unchanged for delta attribution.
#include <cuda_runtime.h>

#define EPS 1e-8f

// Scratch (no allocation allowed).
__device__ float g_h1[256 * 1024];
__device__ float g_h2[256 * 1024];
__device__ float g_pC[4 * 256 * 1024];   // 4 planes L1/L2; 32*256*128 for L3
__device__ float g_Sx[256];
__device__ float g_Sh1[256];
__device__ float g_Sh2[256];
__device__ float g_Sw1[1024];
__device__ float g_Sw2[1024];
__device__ float g_Sw3[128];

// ---------------------------------------------------------------------------
// Row-sum body (tree-reduced), 128 threads per row-block.
__device__ __forceinline__ void rowsum_body(const float* __restrict__ A,
                                            float* __restrict__ S,
                                            int row, int D)
{
    const float4* a = reinterpret_cast<const float4*>(A + (size_t)row * D);
    const int nq = D >> 2;
    float s = 0.0f;
    for (int q = threadIdx.x; q < nq; q += blockDim.x) {
        float4 v = a[q];
        s += (v.x + v.y) + (v.z + v.w);
    }
#pragma unroll
    for (int o = 16; o > 0; o >>= 1) s += __shfl_xor_sync(0xFFFFFFFFu, s, o);
    __shared__ float ws[32];
    const int lane = threadIdx.x & 31, w = threadIdx.x >> 5;
    if (lane == 0) ws[w] = s;
    __syncthreads();
    if (w == 0) {
        s = (lane < (int)(blockDim.x >> 5)) ? ws[lane] : 0.0f;
#pragma unroll
        for (int o = 16; o > 0; o >>= 1) s += __shfl_xor_sync(0xFFFFFFFFu, s, o);
        if (lane == 0) S[row] = s;
    }
}

// Fused row-sums for the four static inputs (all D=1024).
__global__ void rowsum4_kernel(const float* __restrict__ x,  float* __restrict__ Sx,
                               const float* __restrict__ W1, float* __restrict__ Sw1,
                               const float* __restrict__ W2, float* __restrict__ Sw2,
                               const float* __restrict__ W3, float* __restrict__ Sw3,
                               int D)
{
    int b = blockIdx.x;
    if (b < 256)            rowsum_body(x,  Sx,  b,        D);
    else if (b < 256+1024)  rowsum_body(W1, Sw1, b - 256,  D);
    else if (b < 256+2048)  rowsum_body(W2, Sw2, b - 1280, D);
    else                    rowsum_body(W3, Sw3, b - 2304, D);
}

// ---------------------------------------------------------------------------
// Min-sum partial kernel: pC[z,m,n] = sum_{k in z-slice} min(X[m,k], W[n,k]).
// BM=64, BN=128, DK=16, 512 threads (16 warps = 4/SMSP), micro-tile 4x4,
// double-buffered smem. X tile row-major [m][k] (broadcast LDS.128 reads);
// W tile transposed [k][n].
__global__ __launch_bounds__(512)
void tversky_part_kernel(const float* __restrict__ X,
                         const float* __restrict__ W,
                         float* __restrict__ pC,
                         int B, int O, int D, int kspan)
{
    constexpr int BM = 64, BN = 128, DK = 16, TM = 4, TN = 4;
    constexpr int NTX = BN / TN;          // 32 (warp = 32 tx of one ty)
    constexpr int XSTR = DK + 4;          // 20 floats (16B-aligned rows)
    constexpr int WSTR = BN + 4;          // 132 floats (16B-aligned rows)

    const int tid = threadIdx.x;
    const int tx  = tid % NTX;            // 0..31
    const int ty  = tid / NTX;            // 0..15
    const int m0  = blockIdx.y * BM;
    const int n0  = blockIdx.x * BN;
    const int k0  = blockIdx.z * kspan;

    __shared__ __align__(16) float Xs[2][BM][XSTR];   // 10,240 B
    __shared__ __align__(16) float Ws[2][DK][WSTR];   // 16,896 B

    // Loaders (per k-tile): X = 64 rows x 4 quads = 256 float4 (threads 0..255);
    //                       W = 128 rows x 4 quads = 512 float4 (all threads).
    const int xr = tid >> 2, xq = tid & 3;
    const int wr = tid >> 2, wq = tid & 3;

    const float4* Xg = reinterpret_cast<const float4*>(X + (size_t)(m0 + xr) * D + k0) + xq;
    const float4* Wg = reinterpret_cast<const float4*>(W + (size_t)(n0 + wr) * D + k0) + wq;

    float acc[TM][TN];
#pragma unroll
    for (int i = 0; i < TM; i++)
#pragma unroll
        for (int j = 0; j < TN; j++) acc[i][j] = 0.0f;

    const int ntiles = kspan / DK;

    float4 xv = make_float4(0.f, 0.f, 0.f, 0.f);
    float4 wv;
    if (tid < 256) xv = Xg[0];
    wv = Wg[0];

    for (int t = 0; t < ntiles; t++) {
        const int buf = t & 1;

        if (tid < 256)
            *reinterpret_cast<float4*>(&Xs[buf][xr][xq * 4]) = xv;
#pragma unroll
        for (int c = 0; c < 4; c++)
            Ws[buf][wq * 4 + c][wr] = (&wv.x)[c];
        __syncthreads();

        if (t + 1 < ntiles) {
            const int off = (t + 1) * (DK / 4);
            if (tid < 256) xv = Xg[off];
            wv = Wg[off];
        }

#pragma unroll
        for (int kk = 0; kk < DK; kk += 4) {
            float4 xk[TM];
#pragma unroll
            for (int i = 0; i < TM; i++)
                xk[i] = *reinterpret_cast<const float4*>(&Xs[buf][ty * TM + i][kk]);
            float4 wk[4];
#pragma unroll
            for (int c = 0; c < 4; c++)
                wk[c] = *reinterpret_cast<const float4*>(&Ws[buf][kk + c][tx * TN]);
#pragma unroll
            for (int c = 0; c < 4; c++) {
#pragma unroll
                for (int i = 0; i < TM; i++) {
                    const float xi = (&xk[i].x)[c];
                    acc[i][0] += fminf(xi, wk[c].x);
                    acc[i][1] += fminf(xi, wk[c].y);
                    acc[i][2] += fminf(xi, wk[c].z);
                    acc[i][3] += fminf(xi, wk[c].w);
                }
            }
        }
        __syncthreads();
    }

    const size_t zb = (size_t)blockIdx.z * B * O;
#pragma unroll
    for (int i = 0; i < TM; i++) {
        float4 o4;
        o4.x = acc[i][0]; o4.y = acc[i][1]; o4.z = acc[i][2]; o4.w = acc[i][3];
        *reinterpret_cast<float4*>(pC + zb + (size_t)(m0 + ty * TM + i) * O
                                   + (n0 + tx * TN)) = o4;
    }
}

// ---------------------------------------------------------------------------
// Combine NZ=4 partials + epilogue(+relu) + row-sum of result (for next layer).
// One block per output row; 256 threads, 4 cols each (O=1024).
__global__ void combine_epi_rowsum_kernel(const float* __restrict__ pC,
                                          const float* __restrict__ Sx,
                                          const float* __restrict__ Sw,
                                          float* __restrict__ h,
                                          float* __restrict__ Sh,
                                          int B, int O)
{
    const int row = blockIdx.x;
    const int j0  = threadIdx.x * 4;
    const size_t plane = (size_t)B * O;
    const size_t base  = (size_t)row * O + j0;

    float4 c0 = *reinterpret_cast<const float4*>(pC + base);
    float4 c1 = *reinterpret_cast<const float4*>(pC + plane + base);
    float4 c2 = *reinterpret_cast<const float4*>(pC + 2 * plane + base);
    float4 c3 = *reinterpret_cast<const float4*>(pC + 3 * plane + base);
    float4 sw = *reinterpret_cast<const float4*>(Sw + j0);
    const float sx = Sx[row];

    float4 o;
    o.x = fmaxf(((c0.x + c1.x) + (c2.x + c3.x)) / (0.5f * (sx + sw.x) + EPS), 0.0f);
    o.y = fmaxf(((c0.y + c1.y) + (c2.y + c3.y)) / (0.5f * (sx + sw.y) + EPS), 0.0f);
    o.z = fmaxf(((c0.z + c1.z) + (c2.z + c3.z)) / (0.5f * (sx + sw.z) + EPS), 0.0f);
    o.w = fmaxf(((c0.w + c1.w) + (c2.w + c3.w)) / (0.5f * (sx + sw.w) + EPS), 0.0f);
    *reinterpret_cast<float4*>(h + base) = o;

    // Row-sum of h for the next layer's denominator.
    float s = (o.x + o.y) + (o.z + o.w);
#pragma unroll
    for (int off = 16; off > 0; off >>= 1) s += __shfl_xor_sync(0xFFFFFFFFu, s, off);
    __shared__ float ws[8];
    const int lane = threadIdx.x & 31, w = threadIdx.x >> 5;
    if (lane == 0) ws[w] = s;
    __syncthreads();
    if (w == 0) {
        s = (lane < 8) ? ws[lane] : 0.0f;
#pragma unroll
        for (int off = 4; off > 0; off >>= 1) s += __shfl_xor_sync(0xFFFFFFFFu, s, off);
        if (lane == 0) Sh[row] = s;
    }
}

// Combine NZ partials + epilogue (final layer, no relu, no rowsum).
__global__ void combine_final_kernel(const float* __restrict__ pC,
                                     const float* __restrict__ Sx,
                                     const float* __restrict__ Sw,
                                     float* __restrict__ out,
                                     int O, int BO, int nz)
{
    int i = blockIdx.x * blockDim.x + threadIdx.x;
    if (i >= BO) return;
    float c = 0.0f;
    for (int z = 0; z < nz; z++) c += pC[(size_t)z * BO + i];
    const int m = i / O, n = i % O;
    out[i] = c / (0.5f * (Sx[m] + Sw[n]) + EPS);
}

// ---------------------------------------------------------------------------
extern "C" void kernel_launch(void* const* d_in, const int* in_sizes, int n_in,
                              void* d_out, int out_size)
{
    const float* x  = (const float*)d_in[0];   // [256, 1024]
    const float* W1 = (const float*)d_in[1];   // [1024, 1024]
    const float* W2 = (const float*)d_in[2];   // [1024, 1024]
    const float* W3 = (const float*)d_in[3];   // [128, 1024]
    float* out = (float*)d_out;                // [256, 128]

    const int B = 256, H = 1024, C = 128, D = 1024;

    float *h1, *h2, *pC, *Sx, *Sh1, *Sh2, *Sw1, *Sw2, *Sw3;
    cudaGetSymbolAddress((void**)&h1,  g_h1);
    cudaGetSymbolAddress((void**)&h2,  g_h2);
    cudaGetSymbolAddress((void**)&pC,  g_pC);
    cudaGetSymbolAddress((void**)&Sx,  g_Sx);
    cudaGetSymbolAddress((void**)&Sh1, g_Sh1);
    cudaGetSymbolAddress((void**)&Sh2, g_Sh2);
    cudaGetSymbolAddress((void**)&Sw1, g_Sw1);
    cudaGetSymbolAddress((void**)&Sw2, g_Sw2);
    cudaGetSymbolAddress((void**)&Sw3, g_Sw3);

    // Static row sums in one launch.
    rowsum4_kernel<<<256 + 1024 + 1024 + 128, 128>>>(x, Sx, W1, Sw1, W2, Sw2, W3, Sw3, D);

    // Layer 1: x vs W1, split-K=4 (grid 8x4x4 = 128 CTAs), fused combine.
    {
        dim3 grid(H / 128, B / 64, 4);
        tversky_part_kernel<<<grid, 512>>>(x, W1, pC, B, H, D, D / 4);
        combine_epi_rowsum_kernel<<<B, 256>>>(pC, Sx, Sw1, h1, Sh1, B, H);
    }
    // Layer 2: h1 vs W2, split-K=4, fused combine.
    {
        dim3 grid(H / 128, B / 64, 4);
        tversky_part_kernel<<<grid, 512>>>(h1, W2, pC, B, H, H, H / 4);
        combine_epi_rowsum_kernel<<<B, 256>>>(pC, Sh1, Sw2, h2, Sh2, B, H);
    }
    // Layer 3: h2 vs W3, split-K=32 (grid 1x4x32 = 128 CTAs), plain combine.
    {
        const int NZ = 32;
        dim3 grid(C / 128, B / 64, NZ);
        tversky_part_kernel<<<grid, 512>>>(h2, W3, pC, B, C, H, H / NZ);
        combine_final_kernel<<<(B * C + 255) / 256, 256>>>(pC, Sh2, Sw3, out, C, B * C, NZ);
    }
}